// round 9
// baseline (speedup 1.0000x reference)
#include <cuda_runtime.h>
#include <cstdint>
#include <cstddef>

// Problem dims (fixed by the dataset)
#define B_ROWS 65536
#define C_DIM  512
#define K_DIM  512

// ---------------- tiling ----------------
// grid = 512 blocks, each owns 128 rows x FULL N=512 (8 passes of 64 cols).
// block = 256 threads = 8 warps: wm in {0..3}, wn in {0,1}; warp tile 32x32
// = 2 m-frags (m16) x 4 n-frags (n8), mma.m16n8k8.tf32.
constexpr int BM = 128, BN = 64, BK = 16;
constexpr int LDS_R      = 20;                  // smem row stride (20g+tig covers all 32 banks)
constexpr int STAGE_ROWS = BM + BN;             // 192
constexpr int STAGE_F    = STAGE_ROWS * LDS_R;  // 3840 floats = 15360 B
constexpr int NSTAGE     = 3;
constexpr int WACC_OFF   = NSTAGE * STAGE_F;    // 11520
constexpr int SMEM_F     = WACC_OFF + 2 * BM;   // 11776 floats = 47104 B static (<48KB)
constexpr int NT         = K_DIM / BK;          // 32 k-tiles per pass
constexpr int NPASS      = C_DIM / BN;          // 8
constexpr int FT_TOT     = NT * NPASS;          // 256 flat tiles

// ---------------- EMA scan config ----------------
constexpr int EMA_CHUNK  = 128;
constexpr int EMA_WARMUP = 512;   // 0.95^512 ~ 4e-12 << fp32 ulp -> truncation exact

// ---------------- tf32-preconverted scratch (sanctioned __device__ scratch) ----------------
__device__ float g_scratchA[(size_t)B_ROWS * K_DIM];   // tf32-rounded comparison_matrix
__device__ float g_scratchW[(size_t)C_DIM * K_DIM];    // tf32-rounded W_comp

// ============================================================
// helpers
// ============================================================
__device__ __forceinline__ void cp_async16(void* smem_dst, const void* gmem_src) {
    uint32_t s = (uint32_t)__cvta_generic_to_shared(smem_dst);
    asm volatile("cp.async.cg.shared.global [%0], [%1], 16;\n" :: "r"(s), "l"(gmem_src));
}
__device__ __forceinline__ void cp_commit() {
    asm volatile("cp.async.commit_group;\n");
}
template <int N>
__device__ __forceinline__ void cp_wait() {
    asm volatile("cp.async.wait_group %0;\n" :: "n"(N));
}
__device__ __forceinline__ float f2tf32f(float x) {   // round-to-nearest tf32, kept as fp32 bits
    uint32_t u; asm("cvt.rna.tf32.f32 %0, %1;" : "=r"(u) : "f"(x));
    return __uint_as_float(u);
}
__device__ __forceinline__ void mma_tf32(float* c, const uint32_t* a, const uint32_t* b) {
    asm volatile(
        "mma.sync.aligned.m16n8k8.row.col.f32.tf32.tf32.f32 "
        "{%0,%1,%2,%3}, {%4,%5,%6,%7}, {%8,%9}, {%0,%1,%2,%3};\n"
        : "+f"(c[0]), "+f"(c[1]), "+f"(c[2]), "+f"(c[3])
        : "r"(a[0]), "r"(a[1]), "r"(a[2]), "r"(a[3]), "r"(b[0]), "r"(b[1]));
}

// ============================================================
// Kernel 1: EMA target via warmup-truncated parallel scan.
// ============================================================
__global__ void ema_target_kernel(const float* __restrict__ rewards,
                                  float* __restrict__ target)
{
    int t = blockIdx.x * blockDim.x + threadIdx.x;   // 512 workers
    int start = t * EMA_CHUNK;
    if (start >= B_ROWS) return;
    int w0 = start - EMA_WARMUP;
    if (w0 < 0) w0 = 0;

    float ema = 0.0f;
    for (int i = w0; i < start; i++)
        ema = 0.05f * rewards[i] + 0.95f * ema;
    for (int i = start; i < start + EMA_CHUNK; i++) {
        float g = rewards[i];
        ema = 0.05f * g + 0.95f * ema;
        bool gt = g > ema;
        target[2 * i + 0] = gt ? 1.0f : 0.0f;
        target[2 * i + 1] = gt ? 0.0f : 1.0f;
    }
}

// ============================================================
// Kernel 2: tf32 pre-conversion (bandwidth-bound, one RN-cvt per element).
// Converts A into g_scratchA and W into g_scratchW in one grid.
// ============================================================
__global__ void tf32_convert_kernel(const float4* __restrict__ inA,
                                    const float4* __restrict__ inW)
{
    constexpr int NA4 = (B_ROWS * K_DIM) / 4;   // 8388608
    constexpr int NW4 = (C_DIM * K_DIM) / 4;    // 65536
    float4* outA = reinterpret_cast<float4*>(g_scratchA);
    float4* outW = reinterpret_cast<float4*>(g_scratchW);

    int i = blockIdx.x * blockDim.x + threadIdx.x;
    int stride = gridDim.x * blockDim.x;
    for (int j = i; j < NA4; j += stride) {
        float4 v = inA[j];
        v.x = f2tf32f(v.x); v.y = f2tf32f(v.y);
        v.z = f2tf32f(v.z); v.w = f2tf32f(v.w);
        outA[j] = v;
    }
    for (int j = i; j < NW4; j += stride) {
        float4 v = inW[j];
        v.x = f2tf32f(v.x); v.y = f2tf32f(v.y);
        v.z = f2tf32f(v.z); v.w = f2tf32f(v.w);
        outW[j] = v;
    }
}

// ============================================================
// Kernel 3: fused GEMM + relu + blend + wager GEMV.
// Reads pre-rounded tf32 values -> mainloop is pure LDS + HMMA (no cvt).
// 3-stage cp.async ring over 256 flat (pass, k) tiles, cp_wait<1>.
// Conflict-free scalar fragment loads (LDS_R=20).
// ============================================================
__global__ __launch_bounds__(256, 3)
void fused_kernel(const float* __restrict__ prev,
                  const float* __restrict__ cascade,
                  const float* __restrict__ bias,
                  const float* __restrict__ Wwag,
                  const float* __restrict__ bwag,
                  float* __restrict__ wager,
                  float* __restrict__ comp)
{
    __shared__ float smem[SMEM_F];
    float* wacc = smem + WACC_OFF;   // 128 rows x 2

    const int t    = threadIdx.x;
    const int m0   = blockIdx.x * BM;
    const int w    = t >> 5;
    const int wm   = w >> 1;        // 0..3
    const int wn   = w & 1;         // 0..1
    const int lane = t & 31;
    const int g    = lane >> 2;     // 0..7
    const int tig  = lane & 3;      // 0..3

    const float* A = g_scratchA;
    const float* W = g_scratchW;

    // stage fill: 192 rows x 4 x 16B = 768 chunks, 3 per thread
    auto issue_ft = [&](int ft, int s) {
        const int p  = ft >> 5;
        const int kt = ft & 31;
        float* st = smem + s * STAGE_F;
#pragma unroll
        for (int i = 0; i < 3; i++) {
            int c   = t + 256 * i;      // 0..767
            int row = c >> 2;
            int q   = (c & 3) * 4;
            const float* src = (row < BM)
                ? (A + (size_t)(m0 + row) * K_DIM + kt * BK + q)
                : (W + (size_t)(p * BN + (row - BM)) * K_DIM + kt * BK + q);
            cp_async16(st + row * LDS_R + q, src);
        }
        cp_commit();
    };

    issue_ft(0, 0);
    issue_ft(1, 1);
    wacc[t] = 0.0f;   // 256 entries, 256 threads (visible by first mainloop barrier)

    const float r   = *cascade;
    const float omr = 1.0f - r;

    float acc[2][4][4];
#pragma unroll
    for (int mf = 0; mf < 2; mf++)
#pragma unroll
        for (int nf = 0; nf < 4; nf++)
#pragma unroll
            for (int e = 0; e < 4; e++)
                acc[mf][nf][e] = 0.0f;

    int scur = 0;   // stage of flat-tile ft; (scur+2)%3 is the reissue target
    for (int ft = 0; ft < FT_TOT; ft++) {
        cp_wait<1>();
        __syncthreads();             // tile ft visible everywhere; stage (ft-1)%3 fully consumed

        if (ft + 2 < FT_TOT) {
            int snx = scur + 2; if (snx >= 3) snx -= 3;
            issue_ft(ft + 2, snx);
        }

        const float* st = smem + scur * STAGE_F;
#pragma unroll
        for (int kk = 0; kk < 2; kk++) {
            const int ko = kk * 8;
            uint32_t af[2][4], bf[4][2];
#pragma unroll
            for (int mf = 0; mf < 2; mf++) {
                const float* ar = st + (wm * 32 + mf * 16 + g) * LDS_R + ko;
                af[mf][0] = __float_as_uint(ar[tig]);
                af[mf][1] = __float_as_uint(ar[8 * LDS_R + tig]);
                af[mf][2] = __float_as_uint(ar[tig + 4]);
                af[mf][3] = __float_as_uint(ar[8 * LDS_R + tig + 4]);
            }
#pragma unroll
            for (int nf = 0; nf < 4; nf++) {
                const float* br = st + (BM + wn * 32 + nf * 8 + g) * LDS_R + ko;
                bf[nf][0] = __float_as_uint(br[tig]);
                bf[nf][1] = __float_as_uint(br[tig + 4]);
            }
#pragma unroll
            for (int mf = 0; mf < 2; mf++)
#pragma unroll
                for (int nf = 0; nf < 4; nf++)
                    mma_tf32(acc[mf][nf], af[mf], bf[nf]);
        }

        // ---- pass epilogue (kt == 31): registers -> gmem, no barrier needed ----
        if ((ft & 31) == 31) {
            const int p = ft >> 5;
#pragma unroll
            for (int mf = 0; mf < 2; mf++) {
#pragma unroll
                for (int half = 0; half < 2; half++) {
                    const int lr = wm * 32 + mf * 16 + g + half * 8;
                    const size_t gr = (size_t)(m0 + lr);
                    float wp0 = 0.0f, wp1 = 0.0f;
#pragma unroll
                    for (int nf = 0; nf < 4; nf++) {
                        const int lc = p * BN + wn * 32 + nf * 8 + 2 * tig;
                        const float c0 = acc[mf][nf][half * 2 + 0];
                        const float c1 = acc[mf][nf][half * 2 + 1];
                        const float2 bv = *reinterpret_cast<const float2*>(bias + lc);
                        const float2 pv = *reinterpret_cast<const float2*>(
                            prev + gr * C_DIM + lc);
                        const float h0 = fmaxf(c0 + bv.x, 0.0f);
                        const float h1 = fmaxf(c1 + bv.y, 0.0f);
                        float2 o;
                        o.x = fmaf(r, h0, omr * pv.x);
                        o.y = fmaf(r, h1, omr * pv.y);
                        *reinterpret_cast<float2*>(comp + gr * C_DIM + lc) = o;
                        const float2 w0v = *reinterpret_cast<const float2*>(Wwag + lc);
                        const float2 w1v = *reinterpret_cast<const float2*>(Wwag + C_DIM + lc);
                        wp0 += o.x * w0v.x + o.y * w0v.y;
                        wp1 += o.x * w1v.x + o.y * w1v.y;
                    }
                    atomicAdd(&wacc[lr * 2 + 0], wp0);
                    atomicAdd(&wacc[lr * 2 + 1], wp1);
                }
            }
#pragma unroll
            for (int mf = 0; mf < 2; mf++)
#pragma unroll
                for (int nf = 0; nf < 4; nf++)
#pragma unroll
                    for (int e = 0; e < 4; e++)
                        acc[mf][nf][e] = 0.0f;
        }

        if (++scur == 3) scur = 0;
    }

    __syncthreads();   // all wacc contributions visible
    if (t < BM) {
        const size_t gr = (size_t)(m0 + t);
        wager[gr * 2 + 0] = wacc[t * 2 + 0] + bwag[0];
        wager[gr * 2 + 1] = wacc[t * 2 + 1] + bwag[1];
    }
}

// ============================================================
// Launch — three launches, no statics, no attributes, no allocs.
// Inputs (metadata order):
//  0 comparison_matrix [B,512] f32   1 prev_comparison [B,512] f32
//  2 cascade_rate [1] f32            3 rewards [B] f32
//  4 W_comp [512,512] f32            5 b_comp [512] f32
//  6 W_wager [2,512] f32             7 b_wager [2] f32
// Output: concat( wager [B,2], comparison_out [B,512], target [B,2] ) f32
// ============================================================
extern "C" void kernel_launch(void* const* d_in, const int* in_sizes, int n_in,
                              void* d_out, int out_size)
{
    const float* A    = (const float*)d_in[0];
    const float* prev = (const float*)d_in[1];
    const float* casc = (const float*)d_in[2];
    const float* rew  = (const float*)d_in[3];
    const float* W    = (const float*)d_in[4];
    const float* bc   = (const float*)d_in[5];
    const float* Ww   = (const float*)d_in[6];
    const float* bw   = (const float*)d_in[7];

    float* out    = (float*)d_out;
    float* wager  = out;                                                // [B,2]
    float* comp   = out + (size_t)B_ROWS * 2;                           // [B,512]
    float* target = out + (size_t)B_ROWS * 2 + (size_t)B_ROWS * C_DIM;  // [B,2]

    ema_target_kernel<<<4, 128>>>(rew, target);
    tf32_convert_kernel<<<2048, 256>>>((const float4*)A, (const float4*)W);
    fused_kernel<<<B_ROWS / BM, 256>>>(prev, casc, bc, Ww, bw, wager, comp);
}

// round 10
// speedup vs baseline: 1.1696x; 1.1696x over previous
#include <cuda_runtime.h>
#include <cstdint>
#include <cstddef>

// Problem dims (fixed by the dataset)
#define B_ROWS 65536
#define C_DIM  512
#define K_DIM  512

// ---------------- tiling ----------------
constexpr int BM = 128, BN = 64, BK = 16;
constexpr int LDS_R      = 20;                  // smem row stride (20g+tig covers all 32 banks)
constexpr int STAGE_ROWS = BM + BN;             // 192
constexpr int STAGE_F    = STAGE_ROWS * LDS_R;  // 3840 floats = 15360 B
constexpr int NSTAGE     = 3;
constexpr int WACC_OFF   = NSTAGE * STAGE_F;    // 11520
constexpr int SMEM_F     = WACC_OFF + 2 * BM;   // 11776 floats = 47104 B static (<48KB)
constexpr int NT         = K_DIM / BK;          // 32 k-tiles per pass
constexpr int NPASS      = C_DIM / BN;          // 8
constexpr int FT_TOT     = NT * NPASS;          // 256 flat tiles

// ---------------- tf32-preconverted W (sanctioned __device__ scratch) ----------------
__device__ float g_scratchW[(size_t)C_DIM * K_DIM];    // tf32-rounded W_comp (1 MB)

// ============================================================
// helpers
// ============================================================
__device__ __forceinline__ void cp_async16(void* smem_dst, const void* gmem_src) {
    uint32_t s = (uint32_t)__cvta_generic_to_shared(smem_dst);
    asm volatile("cp.async.cg.shared.global [%0], [%1], 16;\n" :: "r"(s), "l"(gmem_src));
}
__device__ __forceinline__ void cp_commit() {
    asm volatile("cp.async.commit_group;\n");
}
template <int N>
__device__ __forceinline__ void cp_wait() {
    asm volatile("cp.async.wait_group %0;\n" :: "n"(N));
}
__device__ __forceinline__ uint32_t f2tf32(float x) {   // round-to-nearest tf32 (bits)
    uint32_t u; asm("cvt.rna.tf32.f32 %0, %1;" : "=r"(u) : "f"(x)); return u;
}
__device__ __forceinline__ float f2tf32f(float x) {     // round-to-nearest tf32 (as float)
    uint32_t u; asm("cvt.rna.tf32.f32 %0, %1;" : "=r"(u) : "f"(x));
    return __uint_as_float(u);
}
__device__ __forceinline__ void mma_tf32(float* c, const uint32_t* a, const uint32_t* b) {
    asm volatile(
        "mma.sync.aligned.m16n8k8.row.col.f32.tf32.tf32.f32 "
        "{%0,%1,%2,%3}, {%4,%5,%6,%7}, {%8,%9}, {%0,%1,%2,%3};\n"
        : "+f"(c[0]), "+f"(c[1]), "+f"(c[2]), "+f"(c[3])
        : "r"(a[0]), "r"(a[1]), "r"(a[2]), "r"(a[3]), "r"(b[0]), "r"(b[1]));
}

// ============================================================
// Kernel 1: EMA target — smem-staged, latency-optimized.
// 16 blocks x 64 workers; block stages [base-512, base+4096) coalesced into
// smem, then each worker runs its 512-warmup + 64-chunk chain on smem.
// ema_i = 0.05*g_i + 0.95*ema_{i-1}; truncation exact (0.95^512 ~ 4e-12).
// ============================================================
__global__ void ema_target_kernel(const float* __restrict__ rewards,
                                  float* __restrict__ target)
{
    __shared__ float s[4608];                 // 512 warmup + 4096 chunk
    const int b = blockIdx.x;
    const int t = threadIdx.x;                // 0..63
    const int base = b * 4096;

    for (int i = t; i < 4608; i += 64) {
        int g = base - 512 + i;
        if (g >= 0) s[i] = rewards[g];        // block 0: s[0..511] unused garbage, never read
    }
    __syncthreads();

    // worker t owns chunk [base + t*64, base + t*64 + 64)
    const int ic = t * 64 + 512;              // smem idx of chunk start
    int i0 = t * 64;                          // smem idx of warmup start
    if (b == 0 && i0 < 512) i0 = 512;         // truncate at global index 0

    float ema = 0.0f;
    for (int i = i0; i < ic; i++)
        ema = 0.05f * s[i] + 0.95f * ema;

    float2* tgt = reinterpret_cast<float2*>(target);
    const int gi = base + t * 64;
#pragma unroll 4
    for (int j = 0; j < 64; j++) {
        float g = s[ic + j];
        ema = 0.05f * g + 0.95f * ema;
        bool gt = g > ema;
        tgt[gi + j] = make_float2(gt ? 1.0f : 0.0f, gt ? 0.0f : 1.0f);
    }
}

// ============================================================
// Kernel 2: W tf32 pre-round (1 MB, ~2 us). One float4 per thread.
// ============================================================
__global__ void convw_kernel(const float4* __restrict__ inW)
{
    float4* o = reinterpret_cast<float4*>(g_scratchW);
    int i = blockIdx.x * blockDim.x + threadIdx.x;   // 65536 threads, 65536 float4s
    float4 v = inW[i];
    v.x = f2tf32f(v.x); v.y = f2tf32f(v.y);
    v.z = f2tf32f(v.z); v.w = f2tf32f(v.w);
    o[i] = v;
}

// ============================================================
// Kernel 3: fused GEMM + relu + blend + wager GEMV.
// A raw fp32 (cvt in a-fragments, 2x-redundant only); W pre-rounded (bits
// pass straight to MMA). 3-stage cp.async ring over 256 flat (pass,k) tiles,
// cp_wait<1>. Conflict-free scalar fragment loads (LDS_R=20).
// ============================================================
__global__ __launch_bounds__(256, 3)
void fused_kernel(const float* __restrict__ A,
                  const float* __restrict__ prev,
                  const float* __restrict__ cascade,
                  const float* __restrict__ bias,
                  const float* __restrict__ Wwag,
                  const float* __restrict__ bwag,
                  float* __restrict__ wager,
                  float* __restrict__ comp)
{
    __shared__ float smem[SMEM_F];
    float* wacc = smem + WACC_OFF;   // 128 rows x 2

    const int t    = threadIdx.x;
    const int m0   = blockIdx.x * BM;
    const int w    = t >> 5;
    const int wm   = w >> 1;        // 0..3
    const int wn   = w & 1;         // 0..1
    const int lane = t & 31;
    const int g    = lane >> 2;     // 0..7
    const int tig  = lane & 3;      // 0..3

    const float* W = g_scratchW;

    // stage fill: 192 rows x 4 x 16B = 768 chunks, 3 per thread
    auto issue_ft = [&](int ft, int s) {
        const int p  = ft >> 5;
        const int kt = ft & 31;
        float* st = smem + s * STAGE_F;
#pragma unroll
        for (int i = 0; i < 3; i++) {
            int c   = t + 256 * i;      // 0..767
            int row = c >> 2;
            int q   = (c & 3) * 4;
            const float* src = (row < BM)
                ? (A + (size_t)(m0 + row) * K_DIM + kt * BK + q)
                : (W + (size_t)(p * BN + (row - BM)) * K_DIM + kt * BK + q);
            cp_async16(st + row * LDS_R + q, src);
        }
        cp_commit();
    };

    issue_ft(0, 0);
    issue_ft(1, 1);
    wacc[t] = 0.0f;   // visible by first mainloop barrier

    const float r   = *cascade;
    const float omr = 1.0f - r;

    float acc[2][4][4];
#pragma unroll
    for (int mf = 0; mf < 2; mf++)
#pragma unroll
        for (int nf = 0; nf < 4; nf++)
#pragma unroll
            for (int e = 0; e < 4; e++)
                acc[mf][nf][e] = 0.0f;

    int scur = 0;
    for (int ft = 0; ft < FT_TOT; ft++) {
        cp_wait<1>();
        __syncthreads();             // tile ft visible; stage (ft-1)%3 fully consumed

        if (ft + 2 < FT_TOT) {
            int snx = scur + 2; if (snx >= 3) snx -= 3;
            issue_ft(ft + 2, snx);
        }

        const float* st = smem + scur * STAGE_F;
#pragma unroll
        for (int kk = 0; kk < 2; kk++) {
            const int ko = kk * 8;
            uint32_t af[2][4], bf[4][2];
#pragma unroll
            for (int mf = 0; mf < 2; mf++) {
                const float* ar = st + (wm * 32 + mf * 16 + g) * LDS_R + ko;
                af[mf][0] = f2tf32(ar[tig]);
                af[mf][1] = f2tf32(ar[8 * LDS_R + tig]);
                af[mf][2] = f2tf32(ar[tig + 4]);
                af[mf][3] = f2tf32(ar[8 * LDS_R + tig + 4]);
            }
#pragma unroll
            for (int nf = 0; nf < 4; nf++) {
                const float* br = st + (BM + wn * 32 + nf * 8 + g) * LDS_R + ko;
                bf[nf][0] = __float_as_uint(br[tig]);       // pre-rounded
                bf[nf][1] = __float_as_uint(br[tig + 4]);
            }
#pragma unroll
            for (int mf = 0; mf < 2; mf++)
#pragma unroll
                for (int nf = 0; nf < 4; nf++)
                    mma_tf32(acc[mf][nf], af[mf], bf[nf]);
        }

        // ---- pass epilogue (kt == 31): registers -> gmem ----
        if ((ft & 31) == 31) {
            const int p = ft >> 5;
#pragma unroll
            for (int mf = 0; mf < 2; mf++) {
#pragma unroll
                for (int half = 0; half < 2; half++) {
                    const int lr = wm * 32 + mf * 16 + g + half * 8;
                    const size_t gr = (size_t)(m0 + lr);
                    float wp0 = 0.0f, wp1 = 0.0f;
#pragma unroll
                    for (int nf = 0; nf < 4; nf++) {
                        const int lc = p * BN + wn * 32 + nf * 8 + 2 * tig;
                        const float c0 = acc[mf][nf][half * 2 + 0];
                        const float c1 = acc[mf][nf][half * 2 + 1];
                        const float2 bv = *reinterpret_cast<const float2*>(bias + lc);
                        const float2 pv = *reinterpret_cast<const float2*>(
                            prev + gr * C_DIM + lc);
                        const float h0 = fmaxf(c0 + bv.x, 0.0f);
                        const float h1 = fmaxf(c1 + bv.y, 0.0f);
                        float2 o;
                        o.x = fmaf(r, h0, omr * pv.x);
                        o.y = fmaf(r, h1, omr * pv.y);
                        *reinterpret_cast<float2*>(comp + gr * C_DIM + lc) = o;
                        const float2 w0v = *reinterpret_cast<const float2*>(Wwag + lc);
                        const float2 w1v = *reinterpret_cast<const float2*>(Wwag + C_DIM + lc);
                        wp0 += o.x * w0v.x + o.y * w0v.y;
                        wp1 += o.x * w1v.x + o.y * w1v.y;
                    }
                    atomicAdd(&wacc[lr * 2 + 0], wp0);
                    atomicAdd(&wacc[lr * 2 + 1], wp1);
                }
            }
#pragma unroll
            for (int mf = 0; mf < 2; mf++)
#pragma unroll
                for (int nf = 0; nf < 4; nf++)
#pragma unroll
                    for (int e = 0; e < 4; e++)
                        acc[mf][nf][e] = 0.0f;
        }

        if (++scur == 3) scur = 0;
    }

    __syncthreads();   // all wacc contributions visible
    if (t < BM) {
        const size_t gr = (size_t)(m0 + t);
        wager[gr * 2 + 0] = wacc[t * 2 + 0] + bwag[0];
        wager[gr * 2 + 1] = wacc[t * 2 + 1] + bwag[1];
    }
}

// ============================================================
// Launch — three launches, no statics, no attributes, no allocs.
// Inputs (metadata order):
//  0 comparison_matrix [B,512] f32   1 prev_comparison [B,512] f32
//  2 cascade_rate [1] f32            3 rewards [B] f32
//  4 W_comp [512,512] f32            5 b_comp [512] f32
//  6 W_wager [2,512] f32             7 b_wager [2] f32
// Output: concat( wager [B,2], comparison_out [B,512], target [B,2] ) f32
// ============================================================
extern "C" void kernel_launch(void* const* d_in, const int* in_sizes, int n_in,
                              void* d_out, int out_size)
{
    const float* A    = (const float*)d_in[0];
    const float* prev = (const float*)d_in[1];
    const float* casc = (const float*)d_in[2];
    const float* rew  = (const float*)d_in[3];
    const float* W    = (const float*)d_in[4];
    const float* bc   = (const float*)d_in[5];
    const float* Ww   = (const float*)d_in[6];
    const float* bw   = (const float*)d_in[7];

    float* out    = (float*)d_out;
    float* wager  = out;                                                // [B,2]
    float* comp   = out + (size_t)B_ROWS * 2;                           // [B,512]
    float* target = out + (size_t)B_ROWS * 2 + (size_t)B_ROWS * C_DIM;  // [B,2]

    ema_target_kernel<<<16, 64>>>(rew, target);
    convw_kernel<<<256, 256>>>((const float4*)W);
    fused_kernel<<<B_ROWS / BM, 256>>>(A, prev, casc, bc, Ww, bw, wager, comp);
}